// round 16
// baseline (speedup 1.0000x reference)
#include <cuda_runtime.h>
#include <cuda_bf16.h>
#include <cstdint>
#include <cfloat>

#define NSAMP   50000
#define DIMS    3072
#define BROWS   128
#define NCLS    10
#define KC      64            // K elements per smem chunk (64 bf16 = 128B = SW128 row)
#define NKC     48            // 3072 / 64
#define NT4TILES 296          // 296 tiles of N=128 -> 2 perfect waves
#define NT4BASE  37888        // 296*128
#define NT3TILES 127          // ceil((50000-37888)/96) tail tiles of N=96
#define DSTRIDE 50080         // row stride of d2 matrix (>= 37888+127*96 = 50080)
#define MARGIN  8.0f          // >5x worst-case bf16 d2 error bound
#define NTHREADS 384          // 256 consumer + 128 producer
#define NSEG    8             // scan segments per row (pass2a/b grid = 128*NSEG)
#define SEGLEN  6250          // 50000 / 8
#define MAXCAND 1024

// ---------------- device scratch (static globals; no allocation) ----------------
__device__ float g_x2[BROWS];
__device__ __align__(16) __nv_bfloat16 g_xb[NKC * 8192];      // X bf16, SW128-swizzled 16KB chunks
__device__ float g_d2[(size_t)BROWS * DSTRIDE];               // approx d2, 25.6 MB
__device__ unsigned long long g_best[BROWS];                  // packed (d2bits<<32)|idx
__device__ int g_cnt[BROWS];
__device__ int g_cand[BROWS * MAXCAND];

// ---------------- helpers ----------------
__device__ __forceinline__ unsigned smem_u32(const void* p) {
    unsigned a;
    asm("{ .reg .u64 t; cvta.to.shared.u64 t, %1; cvt.u32.u64 %0, t; }" : "=r"(a) : "l"(p));
    return a;
}
__device__ __forceinline__ unsigned sw128(unsigned off) { return off ^ ((off >> 3) & 0x70); }
__device__ __forceinline__ unsigned long long umin64(unsigned long long a, unsigned long long b) {
    return a < b ? a : b;
}

__device__ __forceinline__ void ldsm_x4(unsigned r[4], unsigned addr) {
    asm volatile("ldmatrix.sync.aligned.m8n8.x4.shared.b16 {%0,%1,%2,%3}, [%4];"
                 : "=r"(r[0]), "=r"(r[1]), "=r"(r[2]), "=r"(r[3]) : "r"(addr));
}
__device__ __forceinline__ void ldsm_x2(unsigned r[2], unsigned addr) {
    asm volatile("ldmatrix.sync.aligned.m8n8.x2.shared.b16 {%0,%1}, [%2];"
                 : "=r"(r[0]), "=r"(r[1]) : "r"(addr));
}
__device__ __forceinline__ void mma_bf16(float c[4], const unsigned a[4], const unsigned b[2]) {
    asm volatile(
        "mma.sync.aligned.m16n8k16.row.col.f32.bf16.bf16.f32 "
        "{%0,%1,%2,%3}, {%4,%5,%6,%7}, {%8,%9}, {%0,%1,%2,%3};"
        : "+f"(c[0]), "+f"(c[1]), "+f"(c[2]), "+f"(c[3])
        : "r"(a[0]), "r"(a[1]), "r"(a[2]), "r"(a[3]), "r"(b[0]), "r"(b[1]));
}
__device__ __forceinline__ unsigned pack_bf16x2(float hi, float lo) {
    unsigned r;
    asm("cvt.rn.bf16x2.f32 %0, %1, %2;" : "=r"(r) : "f"(hi), "f"(lo));
    return r;
}
__device__ __forceinline__ void cp_async16(unsigned saddr, const void* gptr) {
    asm volatile("cp.async.ca.shared.global [%0], [%1], 16;" :: "r"(saddr), "l"(gptr) : "memory");
}
__device__ __forceinline__ void cp_async_wait_all() {
    asm volatile("cp.async.wait_all;" ::: "memory");
}
__device__ __forceinline__ void bar_sync(int id) {
    asm volatile("bar.sync %0, %1;" :: "r"(id), "r"(NTHREADS) : "memory");
}
__device__ __forceinline__ void bar_arrive(int id) {
    asm volatile("bar.arrive %0, %1;" :: "r"(id), "r"(NTHREADS) : "memory");
}

// ---------------- kernel 1: X -> bf16 swizzled chunks + ||x||^2 ----------------
// 384 blocks: 3 per row, 1024 elems each. g_x2 pre-zeroed by memset.
__global__ void __launch_bounds__(256) prep_kernel(const float* __restrict__ x) {
    const int b = blockIdx.x, tid = threadIdx.x;
    const int m = b / 3, seg = b % 3;
    float acc = 0.f;
    #pragma unroll
    for (int i = 0; i < 4; i++) {
        int k = seg * 1024 + tid + i * 256;
        float v = x[m * DIMS + k];
        acc += v * v;
        int kc = k >> 6, col = k & 63;
        unsigned sw = sw128((unsigned)(m * 128 + col * 2)) >> 1;   // element index
        g_xb[kc * 8192 + sw] = __float2bfloat16(v);
    }
    #pragma unroll
    for (int o = 16; o; o >>= 1) acc += __shfl_down_sync(0xffffffffu, acc, o);
    __shared__ float part[8];
    if ((tid & 31) == 0) part[tid >> 5] = acc;
    __syncthreads();
    if (tid == 0) {
        float t = 0.f;
        #pragma unroll
        for (int i = 0; i < 8; i++) t += part[i];
        atomicAdd(&g_x2[m], t);
    }
}

// ---------------- pass1 body: warp-specialized bf16 distance GEMM ----------------
// NT = n8 subtiles per consumer warp (4 -> tile N=128, 3 -> tile N=96).
// Warps 0-7: consumers (ldsm + HMMA + d2 epilogue). Warps 8-11: producers
// (LDG fp32 -> bf16 -> STS, cp.async A chunk, exact s2).
template <int NT>
__device__ __forceinline__ void pass1_body(const float* __restrict__ samples, int n0) {
    extern __shared__ __align__(16) unsigned char dynsm[];
    __shared__ float s2[128];

    const int tid = threadIdx.x, lane = tid & 31, wid = tid >> 5;

    const unsigned dynbase = smem_u32(dynsm);
    const unsigned pad = ((dynbase + 1023u) & ~1023u) - dynbase;
    unsigned char* pA = dynsm + pad;                     // A bufs: pA + p*16384
    unsigned char* pB = pA + 32768;                      // B bufs: pB + p*16384
    const unsigned aA = dynbase + pad;
    const unsigned aB = aA + 32768;

    if (wid < 8) {
        // ================= CONSUMERS =================
        const int wm = wid >> 2, wn = wid & 3;           // warp tile: 64(M) x NT*8(N)
        const int a_row  = (lane & 7) + ((lane >> 3) & 1) * 8;
        const int a_koff = (lane >> 4) * 8;
        const int b_row  = (lane & 7);
        const int b_koff = (((lane & 15) >> 3)) * 8;

        float c[4][NT][4];
        #pragma unroll
        for (int mt = 0; mt < 4; mt++)
            #pragma unroll
            for (int nt = 0; nt < NT; nt++)
                #pragma unroll
                for (int r = 0; r < 4; r++) c[mt][nt][r] = 0.f;

        for (int kc = 0; kc < NKC; kc++) {
            const int p = kc & 1;
            bar_sync(4 + p);                             // wait FULL[p]
            const unsigned bA = aA + p * 16384, bB = aB + p * 16384;
            #pragma unroll
            for (int ks = 0; ks < 4; ks++) {
                unsigned a[4][4], b[NT][2];
                #pragma unroll
                for (int mt = 0; mt < 4; mt++) {
                    int row = wm * 64 + mt * 16 + a_row;
                    int ke  = ks * 16 + a_koff;
                    ldsm_x4(a[mt], bA + sw128((unsigned)(row * 128 + ke * 2)));
                }
                #pragma unroll
                for (int nt = 0; nt < NT; nt++) {
                    int row = wn * (NT * 8) + nt * 8 + b_row;
                    int ke  = ks * 16 + b_koff;
                    ldsm_x2(b[nt], bB + sw128((unsigned)(row * 128 + ke * 2)));
                }
                #pragma unroll
                for (int mt = 0; mt < 4; mt++)
                    #pragma unroll
                    for (int nt = 0; nt < NT; nt++)
                        mma_bf16(c[mt][nt], a[mt], b[nt]);
            }
            bar_arrive(2 + p);                           // signal EMPTY[p]
        }

        __syncthreads();                                 // producers published s2

        // epilogue: d2 = x2 + s2 - 2*dot, float2-coalesced (no fused min -> low reg pressure)
        const int g = lane >> 2, cq = lane & 3;
        #pragma unroll
        for (int mt = 0; mt < 4; mt++) {
            int r0 = wm * 64 + mt * 16 + g;
            float x2a = g_x2[r0], x2b = g_x2[r0 + 8];
            #pragma unroll
            for (int nt = 0; nt < NT; nt++) {
                int col = wn * (NT * 8) + nt * 8 + 2 * cq;
                int ng = n0 + col;
                float s2a = s2[col], s2b = s2[col + 1];
                float2 v0, v1;
                v0.x = fmaxf(x2a + s2a - 2.f * c[mt][nt][0], 0.f);
                v0.y = fmaxf(x2a + s2b - 2.f * c[mt][nt][1], 0.f);
                v1.x = fmaxf(x2b + s2a - 2.f * c[mt][nt][2], 0.f);
                v1.y = fmaxf(x2b + s2b - 2.f * c[mt][nt][3], 0.f);
                *(float2*)&g_d2[(size_t)r0 * DSTRIDE + ng] = v0;
                *(float2*)&g_d2[(size_t)(r0 + 8) * DSTRIDE + ng] = v1;
            }
        }
    } else {
        // ================= PRODUCERS =================
        const int ptid = tid - 256;                      // 0..127
        const int q = ptid & 15, rbase = ptid >> 4;      // col-quarter, row base
        const float* tb = samples + (size_t)(n0 + rbase) * DIMS + q * 4;

        float s2p[4 * NT];
        #pragma unroll
        for (int j = 0; j < 4 * NT; j++) s2p[j] = 0.f;

        float4 vb[4 * NT];

        for (int kc = 0; kc < NKC; kc++) {
            const int p = kc & 1;
            const int kb = kc * KC;

            // issue B loads BEFORE waiting: DRAM latency hides under consumer MMA
            #pragma unroll
            for (int j = 0; j < 4 * NT; j++) {
                int n = n0 + rbase + 8 * j;
                vb[j] = (n < NSAMP) ? *(const float4*)(tb + (size_t)(8 * j) * DIMS + kb)
                                    : make_float4(0.f, 0.f, 0.f, 0.f);
            }

            if (kc >= 2) bar_sync(2 + p);                // wait EMPTY[p]

            // A chunk via cp.async (L2-hot)
            {
                unsigned dstA = aA + p * 16384 + ptid * 16;
                const unsigned char* srcA = (const unsigned char*)g_xb + kc * 16384 + ptid * 16;
                #pragma unroll
                for (int i = 0; i < 8; i++)
                    cp_async16(dstA + i * 2048, srcA + i * 2048);
            }

            // convert B to bf16 + swizzled STS, accumulate exact s2
            unsigned char* dB = pB + p * 16384;
            #pragma unroll
            for (int j = 0; j < 4 * NT; j++) {
                float4 v = vb[j];
                s2p[j] = fmaf(v.x, v.x, fmaf(v.y, v.y, fmaf(v.z, v.z, fmaf(v.w, v.w, s2p[j]))));
                uint2 H;
                H.x = pack_bf16x2(v.y, v.x);
                H.y = pack_bf16x2(v.w, v.z);
                *(uint2*)(dB + sw128((unsigned)((rbase + 8 * j) * 128 + q * 8))) = H;
            }

            cp_async_wait_all();
            __threadfence_block();
            bar_arrive(4 + p);                           // signal FULL[p]
        }

        // s2 reduction: 16 threads (same rbase) share each row
        #pragma unroll
        for (int j = 0; j < 4 * NT; j++) {
            float v = s2p[j];
            #pragma unroll
            for (int o = 8; o; o >>= 1) v += __shfl_down_sync(0xffffffffu, v, o, 16);
            if ((lane & 15) == 0) s2[rbase + 8 * j] = v;
        }
        __syncthreads();                                 // matches consumers'
    }
}

// Separate entry points: independent register allocation per tile shape.
__global__ void __launch_bounds__(NTHREADS) pass1_nt4(const float* __restrict__ samples) {
    pass1_body<4>(samples, blockIdx.x * 128);
}
__global__ void __launch_bounds__(NTHREADS) pass1_nt3(const float* __restrict__ samples) {
    pass1_body<3>(samples, NT4BASE + blockIdx.x * 96);
}

// ---------------- pass2a: full-chip parallel per-row packed min ----------------
__global__ void __launch_bounds__(256) pass2a_kernel() {
    __shared__ unsigned long long wred[8];
    const int m = blockIdx.x >> 3, seg = blockIdx.x & 7;
    const int tid = threadIdx.x, lane = tid & 31, wid = tid >> 5;
    const float* drow = &g_d2[(size_t)m * DSTRIDE];
    const int i0 = seg * SEGLEN, i1 = i0 + SEGLEN;

    unsigned long long best = ~0ull;
    for (int i = i0 + tid; i < i1; i += 256) {
        float d = drow[i];
        best = umin64(best, ((unsigned long long)__float_as_uint(d) << 32) | (unsigned)i);
    }
    #pragma unroll
    for (int o = 16; o; o >>= 1) best = umin64(best, __shfl_down_sync(0xffffffffu, best, o));
    if (lane == 0) wred[wid] = best;
    __syncthreads();
    if (tid == 0) {
        unsigned long long b = wred[0];
        #pragma unroll
        for (int i = 1; i < 8; i++) b = umin64(b, wred[i]);
        atomicMin(&g_best[m], b);
    }
}

// ---------------- pass2b: full-chip parallel candidate collect ----------------
__global__ void __launch_bounds__(256) pass2b_kernel() {
    const int m = blockIdx.x >> 3, seg = blockIdx.x & 7;
    const int tid = threadIdx.x;
    const float* drow = &g_d2[(size_t)m * DSTRIDE];
    const int i0 = seg * SEGLEN, i1 = i0 + SEGLEN;
    const float thresh = __uint_as_float((unsigned)(g_best[m] >> 32)) + MARGIN;

    for (int i = i0 + tid; i < i1; i += 256) {
        if (drow[i] <= thresh) {
            int p = atomicAdd(&g_cnt[m], 1);
            if (p < MAXCAND) g_cand[m * MAXCAND + p] = i;
        }
    }
}

// ---------------- pass3: warp-per-candidate exact rescore + outputs ----------------
__global__ void __launch_bounds__(256) pass3_kernel(const float* __restrict__ x,
                                                    const float* __restrict__ samples,
                                                    const void* __restrict__ cls,
                                                    float* __restrict__ out) {
    __shared__ unsigned long long wkey[8];
    __shared__ unsigned long long s_best;

    const int m = blockIdx.x, tid = threadIdx.x, lane = tid & 31, wid = tid >> 5;
    const int cnt = g_cnt[m] < MAXCAND ? g_cnt[m] : MAXCAND;
    const float* xr = x + (size_t)m * DIMS;

    unsigned long long wbest = ~0ull;
    for (int ci = wid; ci < cnt; ci += 8) {
        int idx = g_cand[m * MAXCAND + ci];
        const float* sr = samples + (size_t)idx * DIMS;
        float acc = 0.f;
        #pragma unroll 4
        for (int j = lane; j < DIMS; j += 32) {
            float dx = xr[j] - sr[j];
            acc = fmaf(dx, dx, acc);
        }
        #pragma unroll
        for (int o = 16; o; o >>= 1) acc += __shfl_down_sync(0xffffffffu, acc, o);
        if (lane == 0)
            wbest = umin64(wbest, ((unsigned long long)__float_as_uint(fmaxf(acc, 0.f)) << 32)
                                  | (unsigned)idx);
    }
    if (lane == 0) wkey[wid] = wbest;
    __syncthreads();
    if (tid == 0) {
        unsigned long long b = wkey[0];
        #pragma unroll
        for (int i = 1; i < 8; i++) b = umin64(b, wkey[i]);
        s_best = b;
    }
    __syncthreads();

    const unsigned bidx = (unsigned)(s_best & 0xffffffffu);
    const float d2e = __uint_as_float((unsigned)(s_best >> 32));

    // imgs: out[1280 .. 1280 + 128*3072)
    const float4* src = (const float4*)(samples + (size_t)bidx * DIMS);
    float4* dst = (float4*)(out + BROWS * NCLS + (size_t)m * DIMS);
    #pragma unroll
    for (int i = 0; i < 3; i++) dst[tid + i * 256] = src[tid + i * 256];

    if (tid == 0) {
        out[BROWS * NCLS + BROWS * DIMS + m] = sqrtf(d2e);     // l2s
        // classes dtype detection: int64 little-endian => odd int32 words all zero
        const unsigned* ci = (const unsigned*)cls;
        int nz = 0;
        for (int j = 1; j < 256; j += 2) nz += (ci[j] != 0u) ? 1 : 0;
        int cv;
        if (nz == 0) cv = (int)((const long long*)cls)[bidx];
        else         cv = ((const int*)cls)[bidx];
        #pragma unroll
        for (int j = 0; j < NCLS; j++) out[m * NCLS + j] = (j == cv) ? 1.0f : 0.0f;
    }
}

// ---------------- launcher ----------------
extern "C" void kernel_launch(void* const* d_in, const int* in_sizes, int n_in,
                              void* d_out, int out_size) {
    (void)in_sizes; (void)n_in; (void)out_size;
    const float* x       = (const float*)d_in[0];
    const float* samples = (const float*)d_in[1];
    const void*  cls     = d_in[2];
    float*       out     = (float*)d_out;

    void* p_x2 = nullptr; void* p_best = nullptr; void* p_cnt = nullptr;
    cudaGetSymbolAddress(&p_x2, g_x2);
    cudaGetSymbolAddress(&p_best, g_best);
    cudaGetSymbolAddress(&p_cnt, g_cnt);
    cudaMemsetAsync(p_x2, 0, BROWS * sizeof(float));
    cudaMemsetAsync(p_best, 0xFF, BROWS * sizeof(unsigned long long));
    cudaMemsetAsync(p_cnt, 0, BROWS * sizeof(int));

    cudaFuncSetAttribute(pass1_nt4, cudaFuncAttributeMaxDynamicSharedMemorySize, 66560);
    cudaFuncSetAttribute(pass1_nt3, cudaFuncAttributeMaxDynamicSharedMemorySize, 66560);
    prep_kernel<<<BROWS * 3, 256>>>(x);
    pass1_nt4<<<NT4TILES, NTHREADS, 66560>>>(samples);
    pass1_nt3<<<NT3TILES, NTHREADS, 66560>>>(samples);
    pass2a_kernel<<<BROWS * NSEG, 256>>>();
    pass2b_kernel<<<BROWS * NSEG, 256>>>();
    pass3_kernel<<<BROWS, 256>>>(x, samples, cls, out);
}